// round 17
// baseline (speedup 1.0000x reference)
#include <cuda_runtime.h>

#define NBOX 16384
#define NW   256            // 64-bit words per mask row
#define NBKT 16384          // conf buckets for counting sort
#define NBLK 128            // persistent fixpoint CTAs (must be <= SM count)
#define NBLK_S 64           // sort-side CTAs
#define CONF_THRESH 0.5f
#define PIOU_THRESH 0.5f

typedef unsigned long long u64;

// ---------------- device scratch (static; no allocation) ----------------
__device__ float4 g_seph[NBOX];                    // sorted [start,end,peak,height]
__device__ float  g_conf[NBOX];                    // dense confidence (unsorted)
__device__ int    g_hist[NBKT];                    // zeroed by k_fix tail / static init
__device__ int    g_off[NBKT];
__device__ int    g_cnt[NBKT];                     // zeroed by k_fix tail / static init
__device__ int    g_blist[NBOX];
__device__ int    g_M;                             // zeroed by k_fix tail / static init
__device__ u64    g_mask[(size_t)NBOX * NW];       // 32MB suppression bitmask
__device__ u64    g_D[NW];                         // definitely-kept bitmap
__device__ u64    g_suppD[NW];                     // accumulated suppr(D)
__device__ int    g_ulist[2][NBOX];
__device__ int    g_dlist[2][NBOX];
__device__ int    g_un[2], g_dn[2];
__device__ int    g_done;                          // last-block ticket (monotone)
__device__ int    g_arr_f[NBLK];                   // fix barrier slots
__device__ int    g_flag_f;
__device__ int    g_arr_s[NBLK_S];                 // sort barrier slots
__device__ int    g_flag_s;

__device__ __forceinline__ int bucket_of(float c) {
    int b = (int)(c * 16384.0f);                   // exact pow2 mul; monotone
    return b > 16383 ? 16383 : b;
}

// Distributed-arrival grid barrier (see R16): per-CTA arrival slot (plain store,
// no RMW serialization); CTA0 polls all slots in parallel, releases a flag.
// All values monotone across graph replays; each CTA baselines on its OWN slot.
__device__ __forceinline__ void gridsync_n(int& gen, int nblk,
                                           int* slots, int* flg) {
    int next = gen + 1;
    __syncthreads();
    if (blockIdx.x == 0) {
        if (threadIdx.x == 0) {
            __threadfence();
            *(volatile int*)&slots[0] = next;
        }
        if ((int)threadIdx.x < nblk) {
            while (*(volatile int*)&slots[threadIdx.x] < next) { }
        }
        __syncthreads();
        if (threadIdx.x == 0) {
            __threadfence();
            *(volatile int*)flg = next;
        }
    } else {
        if (threadIdx.x == 0) {
            __threadfence();
            *(volatile int*)&slots[blockIdx.x] = next;
            while (*(volatile int*)flg < next) { }
            __threadfence();
        }
    }
    gen = next;
    __syncthreads();
}

// ========== 1) prep + histogram + (last block) suffix scan ==========
__global__ void __launch_bounds__(256, 1) k_sortinit(const float* __restrict__ in) {
    __shared__ int s_scan[256];
    __shared__ int s_last;
    int tid  = threadIdx.x;
    int gtid = blockIdx.x * 256 + tid;             // 0..16383
    float ci = in[gtid * 5];
    g_conf[gtid] = ci;
    atomicAdd(&g_hist[bucket_of(ci)], 1);          // g_hist zeroed at entry
    __threadfence();                               // order hist atomics < ticket
    __syncthreads();
    if (tid == 0) {
        int t = atomicAdd(&g_done, 1);             // monotone across replays
        s_last = ((t & (NBLK_S - 1)) == NBLK_S - 1);
    }
    __syncthreads();
    if (!s_last) return;
    __threadfence();                               // acquire: all hist visible

    // suffix scan of 16384 buckets; thread t owns buckets [t*64, t*64+64)
    int base = tid * 64;
    int s = 0;
    for (int k = 0; k < 64; k++) s += g_hist[base + k];
    s_scan[tid] = s;
    __syncthreads();
    for (int off = 1; off < 256; off <<= 1) {      // inclusive suffix of partials
        int x = (tid + off < 256) ? s_scan[tid + off] : 0;
        __syncthreads();
        s_scan[tid] += x;
        __syncthreads();
    }
    int run = s_scan[tid] - s;                     // sum of buckets >= base+64
    for (int k = 63; k >= 0; k--) {                // off[b] = #elements in buckets > b
        g_off[base + k] = run;
        run += g_hist[base + k];
    }
}

// ========== 2) bucket scatter + gridsync + exact rank & box scatter ==========
__global__ void __launch_bounds__(256, 1) k_scatterrank(const float* __restrict__ in) {
    __shared__ int s_gen;
    int tid  = threadIdx.x;
    int bid  = blockIdx.x;
    int gtid = bid * 256 + tid;                    // 0..16383
    if (tid == 0) s_gen = *(volatile int*)&g_arr_s[bid];
    __syncthreads();
    int gen = s_gen;

    float ci = g_conf[gtid];
    int myb  = bucket_of(ci);
    int pos  = g_off[myb] + atomicAdd(&g_cnt[myb], 1);   // g_cnt zeroed at entry
    g_blist[pos] = gtid;
    gridsync_n(gen, NBLK_S, g_arr_s, &g_flag_s);

    int base = g_off[myb], len = g_hist[myb];
    int cnt = 0;
    for (int p = base; p < base + len; p++) {
        int j = g_blist[p];
        float cj = g_conf[j];
        cnt += (cj > ci) || (cj == ci && j < gtid); // stable: (conf desc, idx asc)
    }
    int r = base + cnt;
    const float* row = in + (size_t)gtid * 5;
    g_seph[r] = make_float4(row[1], row[2], row[3], row[4]);
    if (ci > CONF_THRESH) atomicAdd(&g_M, 1);      // g_M zeroed at entry
}

// ========== 3) pairwise peak-IoU bitmask, upper-triangular blocks only ==========
__global__ void k_mask() {
    __shared__ float4 cols[64];
    if (blockIdx.x < blockIdx.y) return;           // triangular: halves the work
    int M = g_M;
    if ((int)(blockIdx.y * 64) >= M) return;
    int j0 = blockIdx.x * 64;
    if (j0 >= M) return;
    int r = blockIdx.y * 64 + threadIdx.x;
    cols[threadIdx.x] = g_seph[j0 + threadIdx.x];
    __syncthreads();
    if (r >= M) return;
    float4 a = g_seph[r];
    float area1 = __fmul_rn(__fsub_rn(a.y, a.x), a.w);
    u64 w = 0;
#pragma unroll 4
    for (int k = 0; k < 64; k++) {
        float4 b = cols[k];
        float is = fmaxf(a.x, b.x);
        float ie = fminf(a.y, b.y);
        float il = __fsub_rn(ie, is);
        bool sup = false;
        if (il > 0.0f) {                           // piou>0 requires overlap
            float inter_h    = fminf(a.w, b.w);
            float inter_area = __fmul_rn(il, inter_h);
            float area2      = __fmul_rn(__fsub_rn(b.y, b.x), b.w);
            float union_area = __fsub_rn(__fadd_rn(area1, area2), inter_area);
            float iou        = __fdiv_rn(inter_area, union_area);
            float pd         = fabsf(__fsub_rn(a.z, b.z));
            float us         = fminf(a.x, b.x);
            float ue         = fmaxf(a.y, b.y);
            float ud         = fabsf(__fsub_rn(ue, us));
            float val        = __fsub_rn(iou, __fdiv_rn(pd, ud));
            sup = (val > PIOU_THRESH);
        }
        w |= ((u64)sup) << k;
    }
    int lim = M - j0;
    if (lim < 64) w &= (1ULL << lim) - 1ULL;
    if (r >= j0 && r < j0 + 64) w &= ~(1ULL << (r - j0));
    g_mask[(size_t)r * NW + blockIdx.x] = w;
}

// ========== 4) persistent incremental fixpoint NMS ==========
__device__ __forceinline__ u64 trim_diag(u64 v, int j, int wtop) {
    if (j >= wtop) {                               // diagonal word: keep bits > bj
        int bj = j & 63;
        v = (bj == 63) ? 0ULL : (v & (~0ULL << (bj + 1)));
    }
    return v;
}

__device__ __forceinline__ u64 block_or(u64 v, u64* s_acc) {
#pragma unroll
    for (int o = 16; o > 0; o >>= 1)
        v |= __shfl_down_sync(0xffffffffu, v, o);
    if ((threadIdx.x & 31) == 0) s_acc[threadIdx.x >> 5] = v;
    __syncthreads();
    u64 r = 0ULL;
    if (threadIdx.x == 0) {
#pragma unroll
        for (int k = 0; k < 8; k++) r |= s_acc[k];
    }
    return r;                                      // valid on thread 0 only
}

__global__ void __launch_bounds__(256, 1) k_fix(float4* __restrict__ out) {
    __shared__ u64 s_acc[8];
    __shared__ int s_cont;
    __shared__ int s_gen;
    int tid  = threadIdx.x;
    int bid  = blockIdx.x;
    int gtid = bid * 256 + tid;                    // 0..32767
    if (tid == 0) s_gen = *(volatile int*)&g_arr_f[bid];
    __syncthreads();
    int gen = s_gen;
    int M  = g_M;
    int Mw = (M + 63) >> 6;

    // init
    if (gtid < NW) { g_suppD[gtid] = 0ULL; g_D[gtid] = 0ULL; }
    if (gtid == 0) {
        g_un[0] = g_un[1] = 0;
        g_dn[0] = g_dn[1] = 0;
    }
    gridsync_n(gen, NBLK, g_arr_f, &g_flag_f);

    for (int it = 0;; it++) {
        int e = it & 1;
        if (gtid == 0) g_un[e] = 0;                // next-epoch U counter
        // Phase A: Dnew = valid & ~(suppD | suppr(U_{it-1}))
        for (int w = bid; w < Mw; w += NBLK) {
            int hi   = (w + 1) << 6; if (hi > M) hi = M;
            int wtop = w << 6;
            u64 sup = 0ULL;
            if (it == 0) {                         // U_{-1} = all valid
#pragma unroll 4
                for (int j = tid; j < hi; j += 256)
                    sup |= trim_diag(g_mask[(size_t)j * NW + w], j, wtop);
            } else {
                int n = g_un[1 - e];
                const int* ul = g_ulist[1 - e];
#pragma unroll 4
                for (int p = tid; p < n; p += 256) {
                    int j = ul[p];
                    if (j < hi)
                        sup |= trim_diag(g_mask[(size_t)j * NW + w], j, wtop);
                }
            }
            sup = block_or(sup, s_acc);
            if (tid == 0) {
                sup |= g_suppD[w];
                int lim = M - wtop;
                u64 vm = (lim >= 64) ? ~0ULL : ((1ULL << lim) - 1ULL);
                u64 dn  = vm & ~sup;
                u64 add = dn & ~g_D[w];
                g_D[w] = dn;
                int na = __popcll(add);
                if (na) {
                    int base = atomicAdd(&g_dn[e], na);
                    while (add) {
                        int b = __ffsll((long long)add) - 1;
                        add &= add - 1ULL;
                        g_dlist[e][base++] = wtop + b;
                    }
                }
            }
            __syncthreads();
        }
        gridsync_n(gen, NBLK, g_arr_f, &g_flag_f); // S1: D + dlist complete
        if (gtid == 0) g_dn[1 - e] = 0;
        // Phase B: suppD |= suppr(Delta); build U = P\D
        {
            int n = g_dn[e];
            const int* dl = g_dlist[e];
            for (int w = bid; w < Mw; w += NBLK) {
                int hi   = (w + 1) << 6; if (hi > M) hi = M;
                int wtop = w << 6;
                u64 sup = 0ULL;
#pragma unroll 4
                for (int p = tid; p < n; p += 256) {
                    int j = dl[p];
                    if (j < hi)
                        sup |= trim_diag(g_mask[(size_t)j * NW + w], j, wtop);
                }
                sup = block_or(sup, s_acc);
                if (tid == 0) {
                    u64 sd = g_suppD[w] | sup;
                    g_suppD[w] = sd;
                    int lim = M - wtop;
                    u64 vm = (lim >= 64) ? ~0ULL : ((1ULL << lim) - 1ULL);
                    u64 pn   = vm & ~sd;
                    u64 undec = pn & ~g_D[w];      // U empty <=> converged (D<=P)
                    int nu = __popcll(undec);
                    if (nu) {
                        int base = atomicAdd(&g_un[e], nu);
                        while (undec) {
                            int b = __ffsll((long long)undec) - 1;
                            undec &= undec - 1ULL;
                            g_ulist[e][base++] = wtop + b;
                        }
                    }
                }
                __syncthreads();
            }
        }
        gridsync_n(gen, NBLK, g_arr_f, &g_flag_f); // S2: suppD/ulist complete
        if (tid == 0) s_cont = (*(volatile int*)&g_un[e] > 0);
        __syncthreads();
        if (!s_cont) break;
    }

    // output: keep == D (== P at fixpoint)
    if (gtid < NBOX) {
        u64 kw = g_D[gtid >> 6];
        float4 v = ((kw >> (gtid & 63)) & 1ULL) ? g_seph[gtid]
                                                : make_float4(0.f, 0.f, 0.f, 0.f);
        out[gtid] = v;
    }

    // tail: re-zero sort-side state for the next graph replay. Safe: every CTA
    // read g_M before the first gridsync, and g_hist/g_cnt are not read again
    // until the next launch of k_sortinit/k_scatterrank.
    if (gtid < NBKT) { g_hist[gtid] = 0; g_cnt[gtid] = 0; }
    if (gtid == 0) g_M = 0;
}

extern "C" void kernel_launch(void* const* d_in, const int* in_sizes, int n_in,
                              void* d_out, int out_size) {
    const float* in = (const float*)d_in[0];
    float4* out = (float4*)d_out;
    (void)in_sizes; (void)n_in; (void)out_size;

    k_sortinit   <<<NBLK_S, 256>>>(in);
    k_scatterrank<<<NBLK_S, 256>>>(in);
    k_mask       <<<dim3(256, 256), 64>>>();
    k_fix        <<<NBLK, 256>>>(out);
}